// round 8
// baseline (speedup 1.0000x reference)
#include <cuda_runtime.h>
#include <math.h>
#include <float.h>

// Problem dims
#define LL 64
#define BB 128
#define EE 512
#define HH 256
#define H4 1024
#define DD 512      // 2H
#define NG 2048     // fused gate dim (both directions)
#define NROWS 16384 // 2 sentences * L * B

typedef unsigned long long ull;

// f32x2 packed helpers (exact fp32, 2x fma-pipe throughput)
#define FMA2(d, a, b) asm("fma.rn.f32x2 %0, %1, %2, %0;" : "+l"(d) : "l"(a), "l"(b))
#define PACK2(d, lo, hi) asm("mov.b64 %0, {%1, %2};" : "=l"(d) : "f"(lo), "f"(hi))
#define DUP2(d, x) asm("mov.b64 %0, {%1, %1};" : "=l"(d) : "f"(x))
#define UNPACK2(lo, hi, v) asm("mov.b64 {%0, %1}, %2;" : "=f"(lo), "=f"(hi) : "l"(v))

__device__ __forceinline__ float tanh_fast(float x) {
    float y;
    asm("tanh.approx.f32 %0, %1;" : "=f"(y) : "f"(x));
    return y;
}
__device__ __forceinline__ float sig_fast(float x) {
    return fmaf(0.5f, tanh_fast(0.5f * x), 0.5f);
}

// ---------------- scratch (device globals; no allocation allowed) ----------
__device__ float g_x[2 * LL * BB * EE];          // embedded inputs  (33.5 MB)
__device__ float g_xg[(size_t)2 * LL * BB * NG]; // input-gate GEMM out (134 MB)
__device__ float g_o[2 * LL * BB * DD];          // o1, o2 outputs (L,B,D) (33.5 MB)
// h state, PAIR-INTERLEAVED per (buf, rec): index = pair*512 + k*2 + hi
// (pair p holds batches p and p+64)
__device__ float g_h[2 * 4 * BB * HH];           // double-buffered h state (1 MB)
__device__ float g_mp1[BB * DD];
__device__ float g_attsm[BB * LL];
__device__ unsigned g_sync;
__device__ unsigned g_done;

// ---------------- kernel 0: zero h state ----------------
__global__ void zero_h_kernel() {
    int i = blockIdx.x * blockDim.x + threadIdx.x;
    if (i < 2 * 4 * BB * HH) g_h[i] = 0.0f;
}

// ---------------- kernel 1: embedding gather ----------------
__global__ void gather_kernel(const int* __restrict__ t1, const int* __restrict__ t2,
                              const float* __restrict__ emb) {
    int row = blockIdx.x;            // 0..16383
    int s   = row >> 13;
    int r   = row & 8191;
    int tok = s ? t2[r] : t1[r];
    const float4* src = (const float4*)(emb + (size_t)tok * EE);
    float4* dst = (float4*)(g_x + (size_t)row * EE);
    int tid = threadIdx.x;           // 128 threads, 128 float4 per row
    dst[tid] = src[tid];
}

// ---------------- kernel 2: input projection GEMM (f32x2 packed) ----------
__global__ __launch_bounds__(256) void gemm_kernel(
    const float* __restrict__ Wf, const float* __restrict__ Wb,
    const float* __restrict__ bihf, const float* __restrict__ bhhf,
    const float* __restrict__ bihb, const float* __restrict__ bhhb) {
    __shared__ float As[16][132];   // [k][row]
    __shared__ float Bs[16][132];   // [k][col]

    int bm = blockIdx.x;             // 0..127  (M tiles)
    int bn = blockIdx.y;             // 0..15   (N tiles of 128)
    int n0 = bn * 128;
    int dirb = (n0 >= 1024) ? 1 : 0;
    const float* W = dirb ? Wb : Wf;
    int nW0 = dirb ? (n0 - 1024) : n0;

    const float* A = g_x + (size_t)bm * 128 * EE;
    int tid = threadIdx.x;
    int tr = tid >> 4;               // 0..15 -> rows r0..r0+7 (4 packed pairs)
    int tc = tid & 15;               // 0..15 -> cols c0..c0+7
    int r0 = tr * 8, c0 = tc * 8;

    ull acc2[4][8];
#pragma unroll
    for (int p = 0; p < 4; p++)
#pragma unroll
        for (int c = 0; c < 8; c++) acc2[p][c] = 0ULL;

    for (int k0 = 0; k0 < EE; k0 += 16) {
#pragma unroll
        for (int i = 0; i < 2; i++) {
            int idx = tid + 256 * i;     // 512 float4
            int ar = idx >> 2, k4 = idx & 3;
            float4 v = *(const float4*)(A + (size_t)ar * EE + k0 + k4 * 4);
            As[k4 * 4 + 0][ar] = v.x; As[k4 * 4 + 1][ar] = v.y;
            As[k4 * 4 + 2][ar] = v.z; As[k4 * 4 + 3][ar] = v.w;
        }
#pragma unroll
        for (int i = 0; i < 2; i++) {
            int idx = tid + 256 * i;
            int nr = idx >> 2, k4 = idx & 3;
            float4 v = *(const float4*)(W + (size_t)(nW0 + nr) * EE + k0 + k4 * 4);
            Bs[k4 * 4 + 0][nr] = v.x; Bs[k4 * 4 + 1][nr] = v.y;
            Bs[k4 * 4 + 2][nr] = v.z; Bs[k4 * 4 + 3][nr] = v.w;
        }
        __syncthreads();
#pragma unroll
        for (int kk = 0; kk < 16; kk++) {
            ull apair[4];
            {
                ulonglong2 a0 = *(const ulonglong2*)&As[kk][r0];
                ulonglong2 a1 = *(const ulonglong2*)&As[kk][r0 + 4];
                apair[0] = a0.x; apair[1] = a0.y; apair[2] = a1.x; apair[3] = a1.y;
            }
            float4 bv0 = *(const float4*)&Bs[kk][c0];
            float4 bv1 = *(const float4*)&Bs[kk][c0 + 4];
            ull bd[8];
            DUP2(bd[0], bv0.x); DUP2(bd[1], bv0.y); DUP2(bd[2], bv0.z); DUP2(bd[3], bv0.w);
            DUP2(bd[4], bv1.x); DUP2(bd[5], bv1.y); DUP2(bd[6], bv1.z); DUP2(bd[7], bv1.w);
#pragma unroll
            for (int p = 0; p < 4; p++)
#pragma unroll
                for (int c = 0; c < 8; c++)
                    FMA2(acc2[p][c], apair[p], bd[c]);
        }
        __syncthreads();
    }

    float bs[8];
#pragma unroll
    for (int c = 0; c < 8; c++) {
        int n = n0 + c0 + c;
        bs[c] = dirb ? (bihb[n - 1024] + bhhb[n - 1024]) : (bihf[n] + bhhf[n]);
    }
#pragma unroll
    for (int p = 0; p < 4; p++) {
        float lo[8], hi[8];
#pragma unroll
        for (int c = 0; c < 8; c++) {
            UNPACK2(lo[c], hi[c], acc2[p][c]);
            lo[c] += bs[c]; hi[c] += bs[c];
        }
        size_t row_lo = (size_t)(bm * 128 + r0 + 2 * p) * NG + n0 + c0;
        size_t row_hi = row_lo + NG;
        *(float4*)(g_xg + row_lo)     = make_float4(lo[0], lo[1], lo[2], lo[3]);
        *(float4*)(g_xg + row_lo + 4) = make_float4(lo[4], lo[5], lo[6], lo[7]);
        *(float4*)(g_xg + row_hi)     = make_float4(hi[0], hi[1], hi[2], hi[3]);
        *(float4*)(g_xg + row_hi + 4) = make_float4(hi[4], hi[5], hi[6], hi[7]);
    }
}

// ---------------- kernel 3: persistent LSTM recurrence ----------------
// 128 blocks = 4 scans x 32 hidden-slices. 512 threads/block (4 warps/SMSP).
// Thread (ct = tid&7 unit, bt = tid>>3 pair 0..63): batches (bt, bt+64), 4 gates.
// Accumulators packed along the BATCH PAIR: acc2[g] = (acc[bt][g], acc[bt+64][g]).
// sh_hp holds h pre-packed as pairs -> one LDS.128 = 2 packed multiplicands.
// sh_w holds Whh pre-DUPLICATED (w,w) per gate -> zero pack/dup in inner loop.
#define WST 2052   // sh_w unit stride (floats): 8208B % 128B = 16 -> 8 cts conflict-free
#define HPST 520   // sh_hp pair stride (floats): 2080B % 128B = 32 -> 4 bts conflict-free

__global__ __launch_bounds__(512, 1) void lstm_kernel(const float* __restrict__ Whh_f,
                                                      const float* __restrict__ Whh_b) {
    extern __shared__ float sm[];
    float* sh_w = sm;                     // [8 units][2052] : k*8 + g*2 + {0,1} (dup)
    float* sh_hp = sm + 8 * WST;          // [64 pairs][520] : k*2 + hi

    const int tid = threadIdx.x;
    const int rec = blockIdx.x >> 5;      // (s1,f)(s1,b)(s2,f)(s2,b)
    const int slice = blockIdx.x & 31;
    const int s = rec >> 1;
    const int dir = rec & 1;
    const int ct = tid & 7;               // unit within slice
    const int bt = tid >> 3;              // pair 0..63
    const int j = slice * 8 + ct;         // hidden unit 0..255
    const float* Whh = dir ? Whh_b : Whh_f;

    // Build duplicated-pair weights: sh_w[jj*WST + k*8 + g*2 + {0,1}] = Whh[g*256+slice*8+jj][k]
    for (int idx = tid; idx < 8 * 4 * 256; idx += 512) {
        int jj = idx >> 10;
        int g  = (idx >> 8) & 3;
        int k  = idx & 255;
        float v = Whh[(size_t)(g * 256 + slice * 8 + jj) * HH + k];
        float* wp = sh_w + jj * WST + k * 8 + g * 2;
        wp[0] = v; wp[1] = v;
    }

    const float* wbase = sh_w + ct * WST;
    const float* hbase = sh_hp + bt * HPST;
    float c0 = 0.0f, c1 = 0.0f;

    for (int t = 0; t < 64; ++t) {
        const int l = dir ? (63 - t) : t;

        // prefetch xg for both batches of the pair (independent of barrier)
        const float* xgp = g_xg + ((size_t)(s * 8192 + l * 128)) * NG + dir * 1024 + j;
        float xv0[4], xv1[4];
        {
            const float* xr0 = xgp + (size_t)bt * NG;
            const float* xr1 = xgp + (size_t)(bt + 64) * NG;
#pragma unroll
            for (int g = 0; g < 4; g++) {
                xv0[g] = __ldcg(xr0 + g * 256);
                xv1[g] = __ldcg(xr1 + g * 256);
            }
        }

        // stage h_prev (already pair-interleaved in g_h) into smem; L2-only reads
        const float* hsrc = g_h + (size_t)((t & 1) * 4 + rec) * BB * HH;
#pragma unroll 4
        for (int it = 0; it < 16; it++) {
            int idx = tid + 512 * it;       // 8192 float4 total
            int p = idx >> 7, e4 = idx & 127;
            float4 v = __ldcg((const float4*)(hsrc + (size_t)p * 512 + e4 * 4));
            *(float4*)(sh_hp + p * HPST + e4 * 4) = v;
        }

        // init acc: packed along batch pair
        ull acc2[4];
#pragma unroll
        for (int g = 0; g < 4; g++) PACK2(acc2[g], xv0[g], xv1[g]);
        __syncthreads();

        // gates += h_prev @ Whh^T  (2 k-steps per iter, zero packing ops)
#pragma unroll 8
        for (int k2 = 0; k2 < 128; ++k2) {
            ulonglong2 hv = *(const ulonglong2*)(hbase + k2 * 4);   // pairs k, k+1
            ulonglong2 wa = *(const ulonglong2*)(wbase + k2 * 16);      // k: g0,g1
            ulonglong2 wb = *(const ulonglong2*)(wbase + k2 * 16 + 4);  // k: g2,g3
            ulonglong2 wc = *(const ulonglong2*)(wbase + k2 * 16 + 8);  // k+1: g0,g1
            ulonglong2 wd = *(const ulonglong2*)(wbase + k2 * 16 + 12); // k+1: g2,g3
            FMA2(acc2[0], hv.x, wa.x);
            FMA2(acc2[1], hv.x, wa.y);
            FMA2(acc2[2], hv.x, wb.x);
            FMA2(acc2[3], hv.x, wb.y);
            FMA2(acc2[0], hv.y, wc.x);
            FMA2(acc2[1], hv.y, wc.y);
            FMA2(acc2[2], hv.y, wd.x);
            FMA2(acc2[3], hv.y, wd.y);
        }

        // nonlinearity + state update + writes
        float* hdst = g_h + (size_t)(((t + 1) & 1) * 4 + rec) * BB * HH;
        float* odst = g_o + (size_t)s * LL * BB * DD + (size_t)l * BB * DD + dir * HH + j;
        float v0[4], v1[4];
#pragma unroll
        for (int g = 0; g < 4; g++) UNPACK2(v0[g], v1[g], acc2[g]);
        {
            float ig = sig_fast(v0[0]), fg = sig_fast(v0[1]);
            float gg = tanh_fast(v0[2]), og = sig_fast(v0[3]);
            c0 = fmaf(fg, c0, ig * gg);
            float h = og * tanh_fast(c0);
            hdst[bt * 512 + j * 2 + 0] = h;
            odst[(size_t)bt * DD] = h;
        }
        {
            float ig = sig_fast(v1[0]), fg = sig_fast(v1[1]);
            float gg = tanh_fast(v1[2]), og = sig_fast(v1[3]);
            c1 = fmaf(fg, c1, ig * gg);
            float h = og * tanh_fast(c1);
            hdst[bt * 512 + j * 2 + 1] = h;
            odst[(size_t)(bt + 64) * DD] = h;
        }

        // global barrier (all 128 blocks co-resident at 1/SM)
        __syncthreads();   // all threads' stores issued before arrival
        if (tid == 0) {
            __threadfence();
            atomicAdd(&g_sync, 1u);
            unsigned target = 128u * (unsigned)(t + 1);
            while (*((volatile unsigned*)&g_sync) < target) { }
            __threadfence();
        }
        __syncthreads();
    }

    // self-reset for graph replays
    if (tid == 0) {
        unsigned old = atomicAdd(&g_done, 1u);
        if (old == 127u) {
            g_done = 0u;
            g_sync = 0u;
            __threadfence();
        }
    }
}

// ---------------- kernel 4: mp1 = max over time of o1 ----------------
__global__ void mp1_kernel() {
    int b = blockIdx.x;
    for (int d = threadIdx.x; d < DD; d += blockDim.x) {
        float m = -FLT_MAX;
#pragma unroll 8
        for (int l = 0; l < LL; l++)
            m = fmaxf(m, g_o[(size_t)l * BB * DD + b * DD + d]);
        g_mp1[b * DD + d] = m;
    }
}

// ---------------- kernel 5: attention + softmax (raw-reshape semantics) ----
__global__ void att_kernel() {
    __shared__ float smp[DD];
    __shared__ float sat[LL];
    int b = blockIdx.x, l = threadIdx.x;   // 64 threads
    const float* o2 = g_o + (size_t)LL * BB * DD;
    for (int d = l; d < DD; d += LL) smp[d] = g_mp1[b * DD + d];
    __syncthreads();
    float a = 0.0f;
    for (int d = 0; d < DD; d++)
        a = fmaf(smp[d], o2[(size_t)b * DD * LL + d * LL + l], a);
    sat[l] = a;
    __syncthreads();
    float mx = -FLT_MAX;
    for (int i = 0; i < LL; i++) mx = fmaxf(mx, sat[i]);
    float ssum = 0.0f;
    for (int i = 0; i < LL; i++) ssum += expf(sat[i] - mx);
    g_attsm[b * LL + l] = expf(a - mx) / ssum;
}

// ---------------- kernel 6: new_pool + sim (fused) ----------------
__global__ void sim_kernel(float* __restrict__ out) {
    __shared__ float sal[LL];
    __shared__ float red[256];
    int b = blockIdx.x, tid = threadIdx.x;
    if (tid < LL) sal[tid] = g_attsm[b * LL + tid];
    __syncthreads();
    const float* o2 = g_o + (size_t)LL * BB * DD;
    float local = 0.0f;
    for (int d = tid; d < DD; d += 256) {
        float np = 0.0f;
#pragma unroll 8
        for (int l = 0; l < LL; l++)
            np = fmaf(sal[l], o2[(size_t)b * LL * DD + l * DD + d], np);
        local += fabsf(g_mp1[b * DD + d] - np);
    }
    red[tid] = local;
    __syncthreads();
    for (int s2 = 128; s2 > 0; s2 >>= 1) {
        if (tid < s2) red[tid] += red[tid + s2];
        __syncthreads();
    }
    if (tid == 0) out[b] = expf(-red[0]);
}

// ---------------- kernel 7: commonWords + e1h/e2h ----------------
__global__ void e_kernel(const int* __restrict__ t1, const int* __restrict__ t2,
                         float* __restrict__ out) {
    __shared__ int s1[LL];
    __shared__ int spos[LL];
    __shared__ int smask[LL];
    __shared__ int shas;
    int b = blockIdx.x, tid = threadIdx.x;
    if (tid == 0) shas = 0;
    if (tid < LL) s1[tid] = t1[tid * BB + b];
    __syncthreads();
    if (tid < LL) {
        int tok2 = t2[tid * BB + b];
        int d = -1;
        for (int jj = 0; jj < LL; jj++)
            if (s1[jj] == tok2) d = jj;
        int m = (d > 1) && (tok2 > 0);
        smask[tid] = m;
        spos[tid] = min(max(d, 0), LL - 1);
        if (m) atomicOr(&shas, 1);
    }
    __syncthreads();
    int has = shas;
    const float* o1 = g_o;
    const float* o2 = g_o + (size_t)LL * BB * DD;
    for (int d = tid; d < DD; d += 256) {
        float m1 = -FLT_MAX, m2 = -FLT_MAX;
        for (int i = 0; i < LL; i++) {
            if (smask[i]) {
                m1 = fmaxf(m1, o1[(size_t)spos[i] * BB * DD + b * DD + d]);
                m2 = fmaxf(m2, o2[(size_t)i * BB * DD + b * DD + d]);
            }
        }
        out[128 + b * DD + d] = has ? m1 : 0.0f;
        out[128 + BB * DD + b * DD + d] = has ? m2 : 0.0f;
    }
}

// ---------------- launch ----------------
extern "C" void kernel_launch(void* const* d_in, const int* in_sizes, int n_in,
                              void* d_out, int out_size) {
    const int* t1 = (const int*)d_in[0];
    const int* t2 = (const int*)d_in[1];
    const float* emb = (const float*)d_in[2];
    const float* Wihf = (const float*)d_in[3];
    const float* Whhf = (const float*)d_in[4];
    const float* bihf = (const float*)d_in[5];
    const float* bhhf = (const float*)d_in[6];
    const float* Wihb = (const float*)d_in[7];
    const float* Whhb = (const float*)d_in[8];
    const float* bihb = (const float*)d_in[9];
    const float* bhhb = (const float*)d_in[10];
    float* out = (float*)d_out;

    zero_h_kernel<<<(2 * 4 * BB * HH + 255) / 256, 256>>>();
    gather_kernel<<<NROWS, 128>>>(t1, t2, emb);

    dim3 ggrid(128, 16);
    gemm_kernel<<<ggrid, 256>>>(Wihf, Wihb, bihf, bhhf, bihb, bhhb);

    const int lstm_smem = (8 * WST + 64 * HPST) * 4;  // 198,784 B
    cudaFuncSetAttribute(lstm_kernel, cudaFuncAttributeMaxDynamicSharedMemorySize, lstm_smem);
    lstm_kernel<<<128, 512, lstm_smem>>>(Whhf, Whhb);

    mp1_kernel<<<BB, 128>>>();
    att_kernel<<<BB, LL>>>();
    sim_kernel<<<BB, 256>>>(out);
    e_kernel<<<BB, 256>>>(t1, t2, out);
}

// round 9
// speedup vs baseline: 1.4230x; 1.4230x over previous
#include <cuda_runtime.h>
#include <math.h>
#include <float.h>

// Problem dims
#define LL 64
#define BB 128
#define EE 512
#define HH 256
#define H4 1024
#define DD 512      // 2H
#define NG 2048     // fused gate dim (both directions)
#define NROWS 16384 // 2 sentences * L * B

typedef unsigned long long ull;

// f32x2 packed helpers (exact fp32, 2x fma-pipe throughput)
#define FMA2(d, a, b) asm("fma.rn.f32x2 %0, %1, %2, %0;" : "+l"(d) : "l"(a), "l"(b))
#define PACK2(d, lo, hi) asm("mov.b64 %0, {%1, %2};" : "=l"(d) : "f"(lo), "f"(hi))
#define DUP2(d, x) asm("mov.b64 %0, {%1, %1};" : "=l"(d) : "f"(x))
#define UNPACK2(lo, hi, v) asm("mov.b64 {%0, %1}, %2;" : "=f"(lo), "=f"(hi) : "l"(v))

// cp.async (LDGSTS) helpers: .cg = L2-only (required for cross-SM h coherence)
#define CP_ASYNC16(smem_u32, gptr) \
    asm volatile("cp.async.cg.shared.global [%0], [%1], 16;" :: "r"(smem_u32), "l"(gptr) : "memory")
#define CP_COMMIT() asm volatile("cp.async.commit_group;" ::: "memory")
#define CP_WAIT(n)  asm volatile("cp.async.wait_group %0;" :: "n"(n) : "memory")

__device__ __forceinline__ float tanh_fast(float x) {
    float y;
    asm("tanh.approx.f32 %0, %1;" : "=f"(y) : "f"(x));
    return y;
}
__device__ __forceinline__ float sig_fast(float x) {
    return fmaf(0.5f, tanh_fast(0.5f * x), 0.5f);
}

// ---------------- scratch (device globals; no allocation allowed) ----------
__device__ float g_x[2 * LL * BB * EE];          // embedded inputs  (33.5 MB)
__device__ float g_xg[(size_t)2 * LL * BB * NG]; // input-gate GEMM out (134 MB)
__device__ float g_o[2 * LL * BB * DD];          // o1, o2 outputs (L,B,D) (33.5 MB)
__device__ float g_h[2 * 4 * BB * HH];           // double-buffered h state (1 MB)
__device__ float g_mp1[BB * DD];
__device__ float g_attsm[BB * LL];
__device__ unsigned g_sync;
__device__ unsigned g_done;

// ---------------- kernel 0: zero h state ----------------
__global__ void zero_h_kernel() {
    int i = blockIdx.x * blockDim.x + threadIdx.x;
    if (i < 2 * 4 * BB * HH) g_h[i] = 0.0f;
}

// ---------------- kernel 1: embedding gather ----------------
__global__ void gather_kernel(const int* __restrict__ t1, const int* __restrict__ t2,
                              const float* __restrict__ emb) {
    int row = blockIdx.x;            // 0..16383
    int s   = row >> 13;
    int r   = row & 8191;
    int tok = s ? t2[r] : t1[r];
    const float4* src = (const float4*)(emb + (size_t)tok * EE);
    float4* dst = (float4*)(g_x + (size_t)row * EE);
    int tid = threadIdx.x;           // 128 threads, 128 float4 per row
    dst[tid] = src[tid];
}

// ---------------- kernel 2: input projection GEMM (f32x2 packed, BK=32) ----
// C[row][n] = sum_k g_x[row][k] * W[n][k] + bias[n]
// BM=128, BN=128, BK=32, 256 threads, thread tile 8x8 packed along M.
__global__ __launch_bounds__(256) void gemm_kernel(
    const float* __restrict__ Wf, const float* __restrict__ Wb,
    const float* __restrict__ bihf, const float* __restrict__ bhhf,
    const float* __restrict__ bihb, const float* __restrict__ bhhb) {
    __shared__ float As[32][132];   // [k][row]
    __shared__ float Bs[32][132];   // [k][col]

    int bm = blockIdx.x;             // 0..127  (M tiles)
    int bn = blockIdx.y;             // 0..15   (N tiles of 128)
    int n0 = bn * 128;
    int dirb = (n0 >= 1024) ? 1 : 0;
    const float* W = dirb ? Wb : Wf;
    int nW0 = dirb ? (n0 - 1024) : n0;

    const float* A = g_x + (size_t)bm * 128 * EE;
    int tid = threadIdx.x;
    int tr = tid >> 4;               // 0..15 -> rows r0..r0+7 (4 packed pairs)
    int tc = tid & 15;               // 0..15 -> cols c0..c0+7
    int r0 = tr * 8, c0 = tc * 8;

    ull acc2[4][8];
#pragma unroll
    for (int p = 0; p < 4; p++)
#pragma unroll
        for (int c = 0; c < 8; c++) acc2[p][c] = 0ULL;

    for (int k0 = 0; k0 < EE; k0 += 32) {
        // A tile (128 x 32) -> As[k][row]
#pragma unroll
        for (int i = 0; i < 4; i++) {
            int idx = tid + 256 * i;     // 1024 float4
            int ar = idx >> 3, k4 = idx & 7;
            float4 v = *(const float4*)(A + (size_t)ar * EE + k0 + k4 * 4);
            As[k4 * 4 + 0][ar] = v.x; As[k4 * 4 + 1][ar] = v.y;
            As[k4 * 4 + 2][ar] = v.z; As[k4 * 4 + 3][ar] = v.w;
        }
        // W tile (128 x 32) -> Bs[k][col]
#pragma unroll
        for (int i = 0; i < 4; i++) {
            int idx = tid + 256 * i;
            int nr = idx >> 3, k4 = idx & 7;
            float4 v = *(const float4*)(W + (size_t)(nW0 + nr) * EE + k0 + k4 * 4);
            Bs[k4 * 4 + 0][nr] = v.x; Bs[k4 * 4 + 1][nr] = v.y;
            Bs[k4 * 4 + 2][nr] = v.z; Bs[k4 * 4 + 3][nr] = v.w;
        }
        __syncthreads();
#pragma unroll
        for (int kk = 0; kk < 32; kk++) {
            // 8 rows = 4 packed pairs (rows adjacent in As -> pairs come free)
            ull apair[4];
            {
                ulonglong2 a0 = *(const ulonglong2*)&As[kk][r0];
                ulonglong2 a1 = *(const ulonglong2*)&As[kk][r0 + 4];
                apair[0] = a0.x; apair[1] = a0.y; apair[2] = a1.x; apair[3] = a1.y;
            }
            float4 bv0 = *(const float4*)&Bs[kk][c0];
            float4 bv1 = *(const float4*)&Bs[kk][c0 + 4];
            ull bd[8];
            DUP2(bd[0], bv0.x); DUP2(bd[1], bv0.y); DUP2(bd[2], bv0.z); DUP2(bd[3], bv0.w);
            DUP2(bd[4], bv1.x); DUP2(bd[5], bv1.y); DUP2(bd[6], bv1.z); DUP2(bd[7], bv1.w);
#pragma unroll
            for (int p = 0; p < 4; p++)
#pragma unroll
                for (int c = 0; c < 8; c++)
                    FMA2(acc2[p][c], apair[p], bd[c]);
        }
        __syncthreads();
    }

    float bs[8];
#pragma unroll
    for (int c = 0; c < 8; c++) {
        int n = n0 + c0 + c;
        bs[c] = dirb ? (bihb[n - 1024] + bhhb[n - 1024]) : (bihf[n] + bhhf[n]);
    }
#pragma unroll
    for (int p = 0; p < 4; p++) {
        float lo[8], hi[8];
#pragma unroll
        for (int c = 0; c < 8; c++) {
            UNPACK2(lo[c], hi[c], acc2[p][c]);
            lo[c] += bs[c]; hi[c] += bs[c];
        }
        size_t row_lo = (size_t)(bm * 128 + r0 + 2 * p) * NG + n0 + c0;
        size_t row_hi = row_lo + NG;
        *(float4*)(g_xg + row_lo)     = make_float4(lo[0], lo[1], lo[2], lo[3]);
        *(float4*)(g_xg + row_lo + 4) = make_float4(lo[4], lo[5], lo[6], lo[7]);
        *(float4*)(g_xg + row_hi)     = make_float4(hi[0], hi[1], hi[2], hi[3]);
        *(float4*)(g_xg + row_hi + 4) = make_float4(hi[4], hi[5], hi[6], hi[7]);
    }
}

// ---------------- kernel 3: persistent LSTM recurrence ----------------
// (R6-measured-best structure: 256 threads, gate-packed f32x2, 4 batches/thread)
// + cp.async double-chunked h staging overlapped with the first FMA half.
// 128 blocks = 4 scans x 32 hidden-slices. 256 threads/block (2 warps/SMSP).
// Thread (ct = tid&7 unit, bt = tid>>3 0..31): 4 batches (bt + 32*bi), 4 gates.
// acc packed along gates: acc2[bi][0]=(i,f), acc2[bi][1]=(g,o).
// Whh interleaved in smem as (wi,wf,wg,wo)[k] -> packed weight pairs free.
#define WST 1028                     // sh_w unit stride (bank-spread)
#define HST 260                      // sh_h batch stride

__global__ __launch_bounds__(256, 1) void lstm_kernel(const float* __restrict__ Whh_f,
                                                      const float* __restrict__ Whh_b) {
    extern __shared__ float sm[];
    float* sh_w = sm;                     // [8 units][1028] : k*4 + g
    float* sh_h = sm + 8 * WST;           // [128 batches][260]

    const int tid = threadIdx.x;
    const int rec = blockIdx.x >> 5;      // (s1,f)(s1,b)(s2,f)(s2,b)
    const int slice = blockIdx.x & 31;
    const int s = rec >> 1;
    const int dir = rec & 1;
    const int ct = tid & 7;               // unit within slice
    const int bt = tid >> 3;              // 0..31
    const int j = slice * 8 + ct;         // hidden unit 0..255
    const float* Whh = dir ? Whh_b : Whh_f;
    const unsigned shh_u32 = (unsigned)__cvta_generic_to_shared(sh_h);

    // Build interleaved weights: sh_w[jj*WST + k*4 + g] = Whh[g*256+slice*8+jj][k]
    for (int idx = tid; idx < 32 * 64; idx += 256) {
        int cl = idx >> 6;                // 0..31 : (g, jj)
        int k4 = idx & 63;
        int g = cl >> 3, jj = cl & 7;
        float4 v = *(const float4*)(Whh + (size_t)(g * 256 + slice * 8 + jj) * HH + k4 * 4);
        float* wp = sh_w + jj * WST + k4 * 16 + g;
        wp[0] = v.x; wp[4] = v.y; wp[8] = v.z; wp[12] = v.w;
    }

    const float* wbase = sh_w + ct * WST;
    float c_st[4] = {0.f, 0.f, 0.f, 0.f};

    for (int t = 0; t < 64; ++t) {
        const int l = dir ? (63 - t) : t;

        // stage h_prev via cp.async.cg in two chunks (k 0..127 / 128..255)
        const float* hsrc = g_h + (size_t)((t & 1) * 4 + rec) * BB * HH;
#pragma unroll 4
        for (int it = 0; it < 16; it++) {           // chunk0: k4 0..31
            int idx = tid + 256 * it;               // 4096 float4
            int b = idx >> 5, k4 = idx & 31;
            CP_ASYNC16(shh_u32 + (unsigned)(b * HST + k4 * 4) * 4u,
                       hsrc + (size_t)b * HH + k4 * 4);
        }
        CP_COMMIT();
#pragma unroll 4
        for (int it = 0; it < 16; it++) {           // chunk1: k4 32..63
            int idx = tid + 256 * it;
            int b = idx >> 5, k4 = 32 + (idx & 31);
            CP_ASYNC16(shh_u32 + (unsigned)(b * HST + k4 * 4) * 4u,
                       hsrc + (size_t)b * HH + k4 * 4);
        }
        CP_COMMIT();

        // xg prefetch (independent LDGs, overlap with cp.async)
        const float* xgp = g_xg + ((size_t)(s * 8192 + l * 128)) * NG + dir * 1024 + j;
        float xv0[4], xv1[4], xv2[4], xv3[4];
#pragma unroll
        for (int g = 0; g < 4; g++) {
            xv0[g] = __ldcg(xgp + (size_t)bt * NG + g * 256);
            xv1[g] = __ldcg(xgp + (size_t)(bt + 32) * NG + g * 256);
            xv2[g] = __ldcg(xgp + (size_t)(bt + 64) * NG + g * 256);
            xv3[g] = __ldcg(xgp + (size_t)(bt + 96) * NG + g * 256);
        }

        // init acc with xg: (i,f) and (g,o) packs
        ull acc2[4][2];
        PACK2(acc2[0][0], xv0[0], xv0[1]); PACK2(acc2[0][1], xv0[2], xv0[3]);
        PACK2(acc2[1][0], xv1[0], xv1[1]); PACK2(acc2[1][1], xv1[2], xv1[3]);
        PACK2(acc2[2][0], xv2[0], xv2[1]); PACK2(acc2[2][1], xv2[2], xv2[3]);
        PACK2(acc2[3][0], xv3[0], xv3[1]); PACK2(acc2[3][1], xv3[2], xv3[3]);

        CP_WAIT(1);          // chunk0 landed
        __syncthreads();

        // gates += h_prev @ Whh^T : first half (k4 0..31) while chunk1 streams
#pragma unroll 2
        for (int k4 = 0; k4 < 32; ++k4) {
            float4 hv[4];
#pragma unroll
            for (int bi = 0; bi < 4; bi++)
                hv[bi] = *(const float4*)(sh_h + (bt + 32 * bi) * HST + k4 * 4);
#pragma unroll
            for (int i = 0; i < 4; i++) {
                ulonglong2 wv = *(const ulonglong2*)(wbase + (k4 * 4 + i) * 4);
#pragma unroll
                for (int bi = 0; bi < 4; bi++) {
                    float hs = (i == 0) ? hv[bi].x : (i == 1) ? hv[bi].y
                             : (i == 2) ? hv[bi].z : hv[bi].w;
                    ull hd;
                    DUP2(hd, hs);
                    FMA2(acc2[bi][0], hd, wv.x);
                    FMA2(acc2[bi][1], hd, wv.y);
                }
            }
        }

        CP_WAIT(0);          // chunk1 landed
        __syncthreads();

        // second half (k4 32..63)
#pragma unroll 2
        for (int k4 = 32; k4 < 64; ++k4) {
            float4 hv[4];
#pragma unroll
            for (int bi = 0; bi < 4; bi++)
                hv[bi] = *(const float4*)(sh_h + (bt + 32 * bi) * HST + k4 * 4);
#pragma unroll
            for (int i = 0; i < 4; i++) {
                ulonglong2 wv = *(const ulonglong2*)(wbase + (k4 * 4 + i) * 4);
#pragma unroll
                for (int bi = 0; bi < 4; bi++) {
                    float hs = (i == 0) ? hv[bi].x : (i == 1) ? hv[bi].y
                             : (i == 2) ? hv[bi].z : hv[bi].w;
                    ull hd;
                    DUP2(hd, hs);
                    FMA2(acc2[bi][0], hd, wv.x);
                    FMA2(acc2[bi][1], hd, wv.y);
                }
            }
        }

        // nonlinearity + state update + writes
        float* hdst = g_h + (size_t)(((t + 1) & 1) * 4 + rec) * BB * HH;
        float* odst = g_o + (size_t)s * LL * BB * DD + (size_t)l * BB * DD + dir * HH + j;
#pragma unroll
        for (int bi = 0; bi < 4; bi++) {
            int b = bt + 32 * bi;
            float pi, pf, pg, po;
            UNPACK2(pi, pf, acc2[bi][0]);
            UNPACK2(pg, po, acc2[bi][1]);
            float ig = sig_fast(pi);
            float fg = sig_fast(pf);
            float gg = tanh_fast(pg);
            float og = sig_fast(po);
            float c = fmaf(fg, c_st[bi], ig * gg);
            c_st[bi] = c;
            float h = og * tanh_fast(c);
            hdst[(size_t)b * HH + j] = h;
            odst[(size_t)b * DD] = h;
        }

        // global barrier (all 128 blocks co-resident at 1/SM)
        __syncthreads();   // all threads' stores issued before arrival
        if (tid == 0) {
            __threadfence();
            atomicAdd(&g_sync, 1u);
            unsigned target = 128u * (unsigned)(t + 1);
            while (*((volatile unsigned*)&g_sync) < target) { }
            __threadfence();
        }
        __syncthreads();
    }

    // self-reset for graph replays
    if (tid == 0) {
        unsigned old = atomicAdd(&g_done, 1u);
        if (old == 127u) {
            g_done = 0u;
            g_sync = 0u;
            __threadfence();
        }
    }
}

// ---------------- kernel 4: mp1 = max over time of o1 ----------------
__global__ void mp1_kernel() {
    int b = blockIdx.x;
    for (int d = threadIdx.x; d < DD; d += blockDim.x) {
        float m = -FLT_MAX;
#pragma unroll 8
        for (int l = 0; l < LL; l++)
            m = fmaxf(m, g_o[(size_t)l * BB * DD + b * DD + d]);
        g_mp1[b * DD + d] = m;
    }
}

// ---------------- kernel 5: attention + softmax (raw-reshape semantics) ----
__global__ void att_kernel() {
    __shared__ float smp[DD];
    __shared__ float sat[LL];
    int b = blockIdx.x, l = threadIdx.x;   // 64 threads
    const float* o2 = g_o + (size_t)LL * BB * DD;
    for (int d = l; d < DD; d += LL) smp[d] = g_mp1[b * DD + d];
    __syncthreads();
    float a = 0.0f;
    for (int d = 0; d < DD; d++)
        a = fmaf(smp[d], o2[(size_t)b * DD * LL + d * LL + l], a);
    sat[l] = a;
    __syncthreads();
    float mx = -FLT_MAX;
    for (int i = 0; i < LL; i++) mx = fmaxf(mx, sat[i]);
    float ssum = 0.0f;
    for (int i = 0; i < LL; i++) ssum += expf(sat[i] - mx);
    g_attsm[b * LL + l] = expf(a - mx) / ssum;
}

// ---------------- kernel 6: new_pool + sim (fused) ----------------
__global__ void sim_kernel(float* __restrict__ out) {
    __shared__ float sal[LL];
    __shared__ float red[256];
    int b = blockIdx.x, tid = threadIdx.x;
    if (tid < LL) sal[tid] = g_attsm[b * LL + tid];
    __syncthreads();
    const float* o2 = g_o + (size_t)LL * BB * DD;
    float local = 0.0f;
    for (int d = tid; d < DD; d += 256) {
        float np = 0.0f;
#pragma unroll 8
        for (int l = 0; l < LL; l++)
            np = fmaf(sal[l], o2[(size_t)b * LL * DD + l * DD + d], np);
        local += fabsf(g_mp1[b * DD + d] - np);
    }
    red[tid] = local;
    __syncthreads();
    for (int s2 = 128; s2 > 0; s2 >>= 1) {
        if (tid < s2) red[tid] += red[tid + s2];
        __syncthreads();
    }
    if (tid == 0) out[b] = expf(-red[0]);
}

// ---------------- kernel 7: commonWords + e1h/e2h ----------------
__global__ void e_kernel(const int* __restrict__ t1, const int* __restrict__ t2,
                         float* __restrict__ out) {
    __shared__ int s1[LL];
    __shared__ int spos[LL];
    __shared__ int smask[LL];
    __shared__ int shas;
    int b = blockIdx.x, tid = threadIdx.x;
    if (tid == 0) shas = 0;
    if (tid < LL) s1[tid] = t1[tid * BB + b];
    __syncthreads();
    if (tid < LL) {
        int tok2 = t2[tid * BB + b];
        int d = -1;
        for (int jj = 0; jj < LL; jj++)
            if (s1[jj] == tok2) d = jj;
        int m = (d > 1) && (tok2 > 0);
        smask[tid] = m;
        spos[tid] = min(max(d, 0), LL - 1);
        if (m) atomicOr(&shas, 1);
    }
    __syncthreads();
    int has = shas;
    const float* o1 = g_o;
    const float* o2 = g_o + (size_t)LL * BB * DD;
    for (int d = tid; d < DD; d += 256) {
        float m1 = -FLT_MAX, m2 = -FLT_MAX;
        for (int i = 0; i < LL; i++) {
            if (smask[i]) {
                m1 = fmaxf(m1, o1[(size_t)spos[i] * BB * DD + b * DD + d]);
                m2 = fmaxf(m2, o2[(size_t)i * BB * DD + b * DD + d]);
            }
        }
        out[128 + b * DD + d] = has ? m1 : 0.0f;
        out[128 + BB * DD + b * DD + d] = has ? m2 : 0.0f;
    }
}

// ---------------- launch ----------------
extern "C" void kernel_launch(void* const* d_in, const int* in_sizes, int n_in,
                              void* d_out, int out_size) {
    const int* t1 = (const int*)d_in[0];
    const int* t2 = (const int*)d_in[1];
    const float* emb = (const float*)d_in[2];
    const float* Wihf = (const float*)d_in[3];
    const float* Whhf = (const float*)d_in[4];
    const float* bihf = (const float*)d_in[5];
    const float* bhhf = (const float*)d_in[6];
    const float* Wihb = (const float*)d_in[7];
    const float* Whhb = (const float*)d_in[8];
    const float* bihb = (const float*)d_in[9];
    const float* bhhb = (const float*)d_in[10];
    float* out = (float*)d_out;

    zero_h_kernel<<<(2 * 4 * BB * HH + 255) / 256, 256>>>();
    gather_kernel<<<NROWS, 128>>>(t1, t2, emb);

    dim3 ggrid(128, 16);
    gemm_kernel<<<ggrid, 256>>>(Wihf, Wihb, bihf, bhhf, bihb, bhhb);

    const int lstm_smem = (8 * WST + 128 * HST) * 4;  // 166,016 B
    cudaFuncSetAttribute(lstm_kernel, cudaFuncAttributeMaxDynamicSharedMemorySize, lstm_smem);
    lstm_kernel<<<128, 256, lstm_smem>>>(Whhf, Whhb);

    mp1_kernel<<<BB, 128>>>();
    att_kernel<<<BB, LL>>>();
    sim_kernel<<<BB, 256>>>(out);
    e_kernel<<<BB, 256>>>(t1, t2, out);
}

// round 11
// speedup vs baseline: 1.4435x; 1.0144x over previous
#include <cuda_runtime.h>
#include <math.h>
#include <float.h>

// Problem dims
#define LL 64
#define BB 128
#define EE 512
#define HH 256
#define H4 1024
#define DD 512      // 2H
#define NG 2048     // fused gate dim (both directions)
#define NROWS 16384 // 2 sentences * L * B

typedef unsigned long long ull;

// f32x2 packed helpers
#define FMA2(d, a, b) asm("fma.rn.f32x2 %0, %1, %2, %0;" : "+l"(d) : "l"(a), "l"(b))
#define PACK2(d, lo, hi) asm("mov.b64 %0, {%1, %2};" : "=l"(d) : "f"(lo), "f"(hi))
#define DUP2(d, x) asm("mov.b64 %0, {%1, %1};" : "=l"(d) : "f"(x))
#define UNPACK2(lo, hi, v) asm("mov.b64 {%0, %1}, %2;" : "=f"(lo), "=f"(hi) : "l"(v))

// cp.async (LDGSTS) helpers: .cg = L2-only (required for cross-SM h coherence)
#define CP_ASYNC16(smem_u32, gptr) \
    asm volatile("cp.async.cg.shared.global [%0], [%1], 16;" :: "r"(smem_u32), "l"(gptr) : "memory")
#define CP_COMMIT() asm volatile("cp.async.commit_group;" ::: "memory")
#define CP_WAIT(n)  asm volatile("cp.async.wait_group %0;" :: "n"(n) : "memory")

__device__ __forceinline__ float tanh_fast(float x) {
    float y;
    asm("tanh.approx.f32 %0, %1;" : "=f"(y) : "f"(x));
    return y;
}
__device__ __forceinline__ float sig_fast(float x) {
    return fmaf(0.5f, tanh_fast(0.5f * x), 0.5f);
}

// ---------------- scratch (device globals; no allocation allowed) ----------
__device__ float g_x[2 * LL * BB * EE];          // embedded inputs  (33.5 MB)
__device__ float g_xg[(size_t)2 * LL * BB * NG]; // input-gate GEMM out (134 MB)
__device__ float g_o[2 * LL * BB * DD];          // o1, o2 outputs (L,B,D) (33.5 MB)
__device__ float g_h[2 * 4 * BB * HH];           // double-buffered h state (1 MB)
__device__ float g_mp1[BB * DD];
__device__ float g_attsm[BB * LL];
__device__ unsigned g_sync;
__device__ unsigned g_done;

// ---------------- kernel 0: zero h state ----------------
__global__ void zero_h_kernel() {
    int i = blockIdx.x * blockDim.x + threadIdx.x;
    if (i < 2 * 4 * BB * HH) g_h[i] = 0.0f;
}

// ---------------- kernel 1: embedding gather ----------------
__global__ void gather_kernel(const int* __restrict__ t1, const int* __restrict__ t2,
                              const float* __restrict__ emb) {
    int row = blockIdx.x;            // 0..16383
    int s   = row >> 13;
    int r   = row & 8191;
    int tok = s ? t2[r] : t1[r];
    const float4* src = (const float4*)(emb + (size_t)tok * EE);
    float4* dst = (float4*)(g_x + (size_t)row * EE);
    int tid = threadIdx.x;           // 128 threads, 128 float4 per row
    dst[tid] = src[tid];
}

// ---------------- kernel 2: input projection GEMM ----------------
// (f32x2 packed, BK=16, register-staged DOUBLE-BUFFERED smem pipeline)
// C[row][n] = sum_k g_x[row][k] * W[n][k] + bias[n]
// BM=128, BN=128, BK=16, 256 threads, thread tile 8x8 packed along M.
#define GTILE (16 * 132)

__global__ __launch_bounds__(256) void gemm_kernel(
    const float* __restrict__ Wf, const float* __restrict__ Wb,
    const float* __restrict__ bihf, const float* __restrict__ bhhf,
    const float* __restrict__ bihb, const float* __restrict__ bhhb) {
    extern __shared__ float gsm[];
    float* As0 = gsm;                  // [2][16][132]
    float* Bs0 = gsm + 2 * GTILE;      // [2][16][132]

    int bm = blockIdx.x;             // 0..127  (M tiles)
    int bn = blockIdx.y;             // 0..15   (N tiles of 128)
    int n0 = bn * 128;
    int dirb = (n0 >= 1024) ? 1 : 0;
    const float* W = dirb ? Wb : Wf;
    int nW0 = dirb ? (n0 - 1024) : n0;

    const float* A = g_x + (size_t)bm * 128 * EE;
    int tid = threadIdx.x;
    int tr = tid >> 4;               // 0..15 -> rows r0..r0+7 (4 packed pairs)
    int tc = tid & 15;               // 0..15 -> cols c0..c0+7
    int r0 = tr * 8, c0 = tc * 8;

    // per-thread staging indices (2 float4 each for A and B tiles)
    const int ar0 = tid >> 2,        ak0 = tid & 3;          // idx = tid
    const int ar1 = (tid + 256) >> 2, ak1 = tid & 3;         // idx = tid+256

    ull acc2[4][8];
#pragma unroll
    for (int p = 0; p < 4; p++)
#pragma unroll
        for (int c = 0; c < 8; c++) acc2[p][c] = 0ULL;

    // prologue: load tile k0=0 into regs, store to buffer 0
    float4 aR[2], bR[2];
    aR[0] = *(const float4*)(A + (size_t)ar0 * EE + ak0 * 4);
    aR[1] = *(const float4*)(A + (size_t)ar1 * EE + ak1 * 4);
    bR[0] = *(const float4*)(W + (size_t)(nW0 + ar0) * EE + ak0 * 4);
    bR[1] = *(const float4*)(W + (size_t)(nW0 + ar1) * EE + ak1 * 4);
    {
        float* Ad = As0;  float* Bd = Bs0;
        Ad[(ak0 * 4 + 0) * 132 + ar0] = aR[0].x; Ad[(ak0 * 4 + 1) * 132 + ar0] = aR[0].y;
        Ad[(ak0 * 4 + 2) * 132 + ar0] = aR[0].z; Ad[(ak0 * 4 + 3) * 132 + ar0] = aR[0].w;
        Ad[(ak1 * 4 + 0) * 132 + ar1] = aR[1].x; Ad[(ak1 * 4 + 1) * 132 + ar1] = aR[1].y;
        Ad[(ak1 * 4 + 2) * 132 + ar1] = aR[1].z; Ad[(ak1 * 4 + 3) * 132 + ar1] = aR[1].w;
        Bd[(ak0 * 4 + 0) * 132 + ar0] = bR[0].x; Bd[(ak0 * 4 + 1) * 132 + ar0] = bR[0].y;
        Bd[(ak0 * 4 + 2) * 132 + ar0] = bR[0].z; Bd[(ak0 * 4 + 3) * 132 + ar0] = bR[0].w;
        Bd[(ak1 * 4 + 0) * 132 + ar1] = bR[1].x; Bd[(ak1 * 4 + 1) * 132 + ar1] = bR[1].y;
        Bd[(ak1 * 4 + 2) * 132 + ar1] = bR[1].z; Bd[(ak1 * 4 + 3) * 132 + ar1] = bR[1].w;
    }

    for (int it = 0; it < 32; ++it) {
        __syncthreads();             // buffer (it&1) ready for all threads
        if (it < 31) {
            int kn = (it + 1) * 16;  // prefetch next tile (overlaps compute below)
            aR[0] = *(const float4*)(A + (size_t)ar0 * EE + kn + ak0 * 4);
            aR[1] = *(const float4*)(A + (size_t)ar1 * EE + kn + ak1 * 4);
            bR[0] = *(const float4*)(W + (size_t)(nW0 + ar0) * EE + kn + ak0 * 4);
            bR[1] = *(const float4*)(W + (size_t)(nW0 + ar1) * EE + kn + ak1 * 4);
        }

        const float* Asc = As0 + (it & 1) * GTILE;
        const float* Bsc = Bs0 + (it & 1) * GTILE;
#pragma unroll
        for (int kk = 0; kk < 16; kk++) {
            // 8 rows = 4 packed pairs (rows adjacent in As -> pairs come free)
            ull apair[4];
            {
                ulonglong2 a0 = *(const ulonglong2*)&Asc[kk * 132 + r0];
                ulonglong2 a1 = *(const ulonglong2*)&Asc[kk * 132 + r0 + 4];
                apair[0] = a0.x; apair[1] = a0.y; apair[2] = a1.x; apair[3] = a1.y;
            }
            float4 bv0 = *(const float4*)&Bsc[kk * 132 + c0];
            float4 bv1 = *(const float4*)&Bsc[kk * 132 + c0 + 4];
            ull bd[8];
            DUP2(bd[0], bv0.x); DUP2(bd[1], bv0.y); DUP2(bd[2], bv0.z); DUP2(bd[3], bv0.w);
            DUP2(bd[4], bv1.x); DUP2(bd[5], bv1.y); DUP2(bd[6], bv1.z); DUP2(bd[7], bv1.w);
#pragma unroll
            for (int p = 0; p < 4; p++)
#pragma unroll
                for (int c = 0; c < 8; c++)
                    FMA2(acc2[p][c], apair[p], bd[c]);
        }

        if (it < 31) {
            // store staged tile into the OTHER buffer (not being read this iter)
            float* Ad = As0 + ((it + 1) & 1) * GTILE;
            float* Bd = Bs0 + ((it + 1) & 1) * GTILE;
            Ad[(ak0 * 4 + 0) * 132 + ar0] = aR[0].x; Ad[(ak0 * 4 + 1) * 132 + ar0] = aR[0].y;
            Ad[(ak0 * 4 + 2) * 132 + ar0] = aR[0].z; Ad[(ak0 * 4 + 3) * 132 + ar0] = aR[0].w;
            Ad[(ak1 * 4 + 0) * 132 + ar1] = aR[1].x; Ad[(ak1 * 4 + 1) * 132 + ar1] = aR[1].y;
            Ad[(ak1 * 4 + 2) * 132 + ar1] = aR[1].z; Ad[(ak1 * 4 + 3) * 132 + ar1] = aR[1].w;
            Bd[(ak0 * 4 + 0) * 132 + ar0] = bR[0].x; Bd[(ak0 * 4 + 1) * 132 + ar0] = bR[0].y;
            Bd[(ak0 * 4 + 2) * 132 + ar0] = bR[0].z; Bd[(ak0 * 4 + 3) * 132 + ar0] = bR[0].w;
            Bd[(ak1 * 4 + 0) * 132 + ar1] = bR[1].x; Bd[(ak1 * 4 + 1) * 132 + ar1] = bR[1].y;
            Bd[(ak1 * 4 + 2) * 132 + ar1] = bR[1].z; Bd[(ak1 * 4 + 3) * 132 + ar1] = bR[1].w;
        }
    }

    // bias + store
    float bs[8];
#pragma unroll
    for (int c = 0; c < 8; c++) {
        int n = n0 + c0 + c;
        bs[c] = dirb ? (bihb[n - 1024] + bhhb[n - 1024]) : (bihf[n] + bhhf[n]);
    }
#pragma unroll
    for (int p = 0; p < 4; p++) {
        float lo[8], hi[8];
#pragma unroll
        for (int c = 0; c < 8; c++) {
            UNPACK2(lo[c], hi[c], acc2[p][c]);
            lo[c] += bs[c]; hi[c] += bs[c];
        }
        size_t row_lo = (size_t)(bm * 128 + r0 + 2 * p) * NG + n0 + c0;
        size_t row_hi = row_lo + NG;
        *(float4*)(g_xg + row_lo)     = make_float4(lo[0], lo[1], lo[2], lo[3]);
        *(float4*)(g_xg + row_lo + 4) = make_float4(lo[4], lo[5], lo[6], lo[7]);
        *(float4*)(g_xg + row_hi)     = make_float4(hi[0], hi[1], hi[2], hi[3]);
        *(float4*)(g_xg + row_hi + 4) = make_float4(hi[4], hi[5], hi[6], hi[7]);
    }
}

// ---------------- kernel 3: persistent LSTM recurrence (R8 measured-best) --
// 128 blocks = 4 scans x 32 hidden-slices. 256 threads/block (2 warps/SMSP).
// Thread (ct = tid&7 unit, bt = tid>>3 0..31): 4 batches (bt + 32*bi), 4 gates.
// acc packed along gates: acc2[bi][0]=(i,f), acc2[bi][1]=(g,o).
// Whh interleaved in smem as (wi,wf,wg,wo)[k]; cp.async double-chunked h stage.
#define WST 1028                     // sh_w unit stride (bank-spread)
#define HST 260                      // sh_h batch stride

__global__ __launch_bounds__(256, 1) void lstm_kernel(const float* __restrict__ Whh_f,
                                                      const float* __restrict__ Whh_b) {
    extern __shared__ float sm[];
    float* sh_w = sm;                     // [8 units][1028] : k*4 + g
    float* sh_h = sm + 8 * WST;           // [128 batches][260]

    const int tid = threadIdx.x;
    const int rec = blockIdx.x >> 5;      // (s1,f)(s1,b)(s2,f)(s2,b)
    const int slice = blockIdx.x & 31;
    const int s = rec >> 1;
    const int dir = rec & 1;
    const int ct = tid & 7;               // unit within slice
    const int bt = tid >> 3;              // 0..31
    const int j = slice * 8 + ct;         // hidden unit 0..255
    const float* Whh = dir ? Whh_b : Whh_f;
    const unsigned shh_u32 = (unsigned)__cvta_generic_to_shared(sh_h);

    // Build interleaved weights: sh_w[jj*WST + k*4 + g] = Whh[g*256+slice*8+jj][k]
    for (int idx = tid; idx < 32 * 64; idx += 256) {
        int cl = idx >> 6;                // 0..31 : (g, jj)
        int k4 = idx & 63;
        int g = cl >> 3, jj = cl & 7;
        float4 v = *(const float4*)(Whh + (size_t)(g * 256 + slice * 8 + jj) * HH + k4 * 4);
        float* wp = sh_w + jj * WST + k4 * 16 + g;
        wp[0] = v.x; wp[4] = v.y; wp[8] = v.z; wp[12] = v.w;
    }

    const float* wbase = sh_w + ct * WST;
    float c_st[4] = {0.f, 0.f, 0.f, 0.f};

    for (int t = 0; t < 64; ++t) {
        const int l = dir ? (63 - t) : t;

        // stage h_prev via cp.async.cg in two chunks (k 0..127 / 128..255)
        const float* hsrc = g_h + (size_t)((t & 1) * 4 + rec) * BB * HH;
#pragma unroll 4
        for (int it = 0; it < 16; it++) {           // chunk0: k4 0..31
            int idx = tid + 256 * it;               // 4096 float4
            int b = idx >> 5, k4 = idx & 31;
            CP_ASYNC16(shh_u32 + (unsigned)(b * HST + k4 * 4) * 4u,
                       hsrc + (size_t)b * HH + k4 * 4);
        }
        CP_COMMIT();
#pragma unroll 4
        for (int it = 0; it < 16; it++) {           // chunk1: k4 32..63
            int idx = tid + 256 * it;
            int b = idx >> 5, k4 = 32 + (idx & 31);
            CP_ASYNC16(shh_u32 + (unsigned)(b * HST + k4 * 4) * 4u,
                       hsrc + (size_t)b * HH + k4 * 4);
        }
        CP_COMMIT();

        // xg prefetch (independent LDGs, overlap with cp.async)
        const float* xgp = g_xg + ((size_t)(s * 8192 + l * 128)) * NG + dir * 1024 + j;
        float xv0[4], xv1[4], xv2[4], xv3[4];
#pragma unroll
        for (int g = 0; g < 4; g++) {
            xv0[g] = __ldcg(xgp + (size_t)bt * NG + g * 256);
            xv1[g] = __ldcg(xgp + (size_t)(bt + 32) * NG + g * 256);
            xv2[g] = __ldcg(xgp + (size_t)(bt + 64) * NG + g * 256);
            xv3[g] = __ldcg(xgp + (size_t)(bt + 96) * NG + g * 256);
        }

        // init acc with xg: (i,f) and (g,o) packs
        ull acc2[4][2];
        PACK2(acc2[0][0], xv0[0], xv0[1]); PACK2(acc2[0][1], xv0[2], xv0[3]);
        PACK2(acc2[1][0], xv1[0], xv1[1]); PACK2(acc2[1][1], xv1[2], xv1[3]);
        PACK2(acc2[2][0], xv2[0], xv2[1]); PACK2(acc2[2][1], xv2[2], xv2[3]);
        PACK2(acc2[3][0], xv3[0], xv3[1]); PACK2(acc2[3][1], xv3[2], xv3[3]);

        CP_WAIT(1);          // chunk0 landed
        __syncthreads();

        // gates += h_prev @ Whh^T : first half (k4 0..31) while chunk1 streams
#pragma unroll 2
        for (int k4 = 0; k4 < 32; ++k4) {
            float4 hv[4];
#pragma unroll
            for (int bi = 0; bi < 4; bi++)
                hv[bi] = *(const float4*)(sh_h + (bt + 32 * bi) * HST + k4 * 4);
#pragma unroll
            for (int i = 0; i < 4; i++) {
                ulonglong2 wv = *(const ulonglong2*)(wbase + (k4 * 4 + i) * 4);
#pragma unroll
                for (int bi = 0; bi < 4; bi++) {
                    float hs = (i == 0) ? hv[bi].x : (i == 1) ? hv[bi].y
                             : (i == 2) ? hv[bi].z : hv[bi].w;
                    ull hd;
                    DUP2(hd, hs);
                    FMA2(acc2[bi][0], hd, wv.x);
                    FMA2(acc2[bi][1], hd, wv.y);
                }
            }
        }

        CP_WAIT(0);          // chunk1 landed
        __syncthreads();

        // second half (k4 32..63)
#pragma unroll 2
        for (int k4 = 32; k4 < 64; ++k4) {
            float4 hv[4];
#pragma unroll
            for (int bi = 0; bi < 4; bi++)
                hv[bi] = *(const float4*)(sh_h + (bt + 32 * bi) * HST + k4 * 4);
#pragma unroll
            for (int i = 0; i < 4; i++) {
                ulonglong2 wv = *(const ulonglong2*)(wbase + (k4 * 4 + i) * 4);
#pragma unroll
                for (int bi = 0; bi < 4; bi++) {
                    float hs = (i == 0) ? hv[bi].x : (i == 1) ? hv[bi].y
                             : (i == 2) ? hv[bi].z : hv[bi].w;
                    ull hd;
                    DUP2(hd, hs);
                    FMA2(acc2[bi][0], hd, wv.x);
                    FMA2(acc2[bi][1], hd, wv.y);
                }
            }
        }

        // nonlinearity + state update + writes
        float* hdst = g_h + (size_t)(((t + 1) & 1) * 4 + rec) * BB * HH;
        float* odst = g_o + (size_t)s * LL * BB * DD + (size_t)l * BB * DD + dir * HH + j;
#pragma unroll
        for (int bi = 0; bi < 4; bi++) {
            int b = bt + 32 * bi;
            float pi, pf, pg, po;
            UNPACK2(pi, pf, acc2[bi][0]);
            UNPACK2(pg, po, acc2[bi][1]);
            float ig = sig_fast(pi);
            float fg = sig_fast(pf);
            float gg = tanh_fast(pg);
            float og = sig_fast(po);
            float c = fmaf(fg, c_st[bi], ig * gg);
            c_st[bi] = c;
            float h = og * tanh_fast(c);
            hdst[(size_t)b * HH + j] = h;
            odst[(size_t)b * DD] = h;
        }

        // global barrier (all 128 blocks co-resident at 1/SM)
        __syncthreads();   // all threads' stores issued before arrival
        if (tid == 0) {
            __threadfence();
            atomicAdd(&g_sync, 1u);
            unsigned target = 128u * (unsigned)(t + 1);
            while (*((volatile unsigned*)&g_sync) < target) { }
            __threadfence();
        }
        __syncthreads();
    }

    // self-reset for graph replays
    if (tid == 0) {
        unsigned old = atomicAdd(&g_done, 1u);
        if (old == 127u) {
            g_done = 0u;
            g_sync = 0u;
            __threadfence();
        }
    }
}

// ---------------- kernel 4: mp1 = max over time of o1 ----------------
__global__ void mp1_kernel() {
    int b = blockIdx.x;
    for (int d = threadIdx.x; d < DD; d += blockDim.x) {
        float m = -FLT_MAX;
#pragma unroll 8
        for (int l = 0; l < LL; l++)
            m = fmaxf(m, g_o[(size_t)l * BB * DD + b * DD + d]);
        g_mp1[b * DD + d] = m;
    }
}

// ---------------- kernel 5: attention + softmax (raw-reshape semantics) ----
__global__ void att_kernel() {
    __shared__ float smp[DD];
    __shared__ float sat[LL];
    int b = blockIdx.x, l = threadIdx.x;   // 64 threads
    const float* o2 = g_o + (size_t)LL * BB * DD;
    for (int d = l; d < DD; d += LL) smp[d] = g_mp1[b * DD + d];
    __syncthreads();
    float a = 0.0f;
    for (int d = 0; d < DD; d++)
        a = fmaf(smp[d], o2[(size_t)b * DD * LL + d * LL + l], a);
    sat[l] = a;
    __syncthreads();
    float mx = -FLT_MAX;
    for (int i = 0; i < LL; i++) mx = fmaxf(mx, sat[i]);
    float ssum = 0.0f;
    for (int i = 0; i < LL; i++) ssum += expf(sat[i] - mx);
    g_attsm[b * LL + l] = expf(a - mx) / ssum;
}

// ---------------- kernel 6: new_pool + sim (fused) ----------------
__global__ void sim_kernel(float* __restrict__ out) {
    __shared__ float sal[LL];
    __shared__ float red[256];
    int b = blockIdx.x, tid = threadIdx.x;
    if (tid < LL) sal[tid] = g_attsm[b * LL + tid];
    __syncthreads();
    const float* o2 = g_o + (size_t)LL * BB * DD;
    float local = 0.0f;
    for (int d = tid; d < DD; d += 256) {
        float np = 0.0f;
#pragma unroll 8
        for (int l = 0; l < LL; l++)
            np = fmaf(sal[l], o2[(size_t)b * LL * DD + l * DD + d], np);
        local += fabsf(g_mp1[b * DD + d] - np);
    }
    red[tid] = local;
    __syncthreads();
    for (int s2 = 128; s2 > 0; s2 >>= 1) {
        if (tid < s2) red[tid] += red[tid + s2];
        __syncthreads();
    }
    if (tid == 0) out[b] = expf(-red[0]);
}

// ---------------- kernel 7: commonWords + e1h/e2h ----------------
__global__ void e_kernel(const int* __restrict__ t1, const int* __restrict__ t2,
                         float* __restrict__ out) {
    __shared__ int s1[LL];
    __shared__ int spos[LL];
    __shared__ int smask[LL];
    __shared__ int shas;
    int b = blockIdx.x, tid = threadIdx.x;
    if (tid == 0) shas = 0;
    if (tid < LL) s1[tid] = t1[tid * BB + b];
    __syncthreads();
    if (tid < LL) {
        int tok2 = t2[tid * BB + b];
        int d = -1;
        for (int jj = 0; jj < LL; jj++)
            if (s1[jj] == tok2) d = jj;
        int m = (d > 1) && (tok2 > 0);
        smask[tid] = m;
        spos[tid] = min(max(d, 0), LL - 1);
        if (m) atomicOr(&shas, 1);
    }
    __syncthreads();
    int has = shas;
    const float* o1 = g_o;
    const float* o2 = g_o + (size_t)LL * BB * DD;
    for (int d = tid; d < DD; d += 256) {
        float m1 = -FLT_MAX, m2 = -FLT_MAX;
        for (int i = 0; i < LL; i++) {
            if (smask[i]) {
                m1 = fmaxf(m1, o1[(size_t)spos[i] * BB * DD + b * DD + d]);
                m2 = fmaxf(m2, o2[(size_t)i * BB * DD + b * DD + d]);
            }
        }
        out[128 + b * DD + d] = has ? m1 : 0.0f;
        out[128 + BB * DD + b * DD + d] = has ? m2 : 0.0f;
    }
}

// ---------------- launch ----------------
extern "C" void kernel_launch(void* const* d_in, const int* in_sizes, int n_in,
                              void* d_out, int out_size) {
    const int* t1 = (const int*)d_in[0];
    const int* t2 = (const int*)d_in[1];
    const float* emb = (const float*)d_in[2];
    const float* Wihf = (const float*)d_in[3];
    const float* Whhf = (const float*)d_in[4];
    const float* bihf = (const float*)d_in[5];
    const float* bhhf = (const float*)d_in[6];
    const float* Wihb = (const float*)d_in[7];
    const float* Whhb = (const float*)d_in[8];
    const float* bihb = (const float*)d_in[9];
    const float* bhhb = (const float*)d_in[10];
    float* out = (float*)d_out;

    zero_h_kernel<<<(2 * 4 * BB * HH + 255) / 256, 256>>>();
    gather_kernel<<<NROWS, 128>>>(t1, t2, emb);

    const int gemm_smem = 4 * GTILE * 4;   // 33,792 B * 2 arrays = 67,584 B
    cudaFuncSetAttribute(gemm_kernel, cudaFuncAttributeMaxDynamicSharedMemorySize, gemm_smem);
    dim3 ggrid(128, 16);
    gemm_kernel<<<ggrid, 256, gemm_smem>>>(Wihf, Wihb, bihf, bhhf, bihb, bhhb);

    const int lstm_smem = (8 * WST + 128 * HST) * 4;  // 166,016 B
    cudaFuncSetAttribute(lstm_kernel, cudaFuncAttributeMaxDynamicSharedMemorySize, lstm_smem);
    lstm_kernel<<<128, 256, lstm_smem>>>(Whhf, Whhb);

    mp1_kernel<<<BB, 128>>>();
    att_kernel<<<BB, LL>>>();
    sim_kernel<<<BB, 256>>>(out);
    e_kernel<<<BB, 256>>>(t1, t2, out);
}

// round 12
// speedup vs baseline: 1.5476x; 1.0721x over previous
#include <cuda_runtime.h>
#include <math.h>
#include <float.h>

// Problem dims
#define LL 64
#define BB 128
#define EE 512
#define HH 256
#define H4 1024
#define DD 512      // 2H
#define NG 2048     // fused gate dim (both directions)
#define NROWS 16384 // 2 sentences * L * B

typedef unsigned long long ull;

// f32x2 packed helpers
#define FMA2(d, a, b) asm("fma.rn.f32x2 %0, %1, %2, %0;" : "+l"(d) : "l"(a), "l"(b))
#define PACK2(d, lo, hi) asm("mov.b64 %0, {%1, %2};" : "=l"(d) : "f"(lo), "f"(hi))
#define DUP2(d, x) asm("mov.b64 %0, {%1, %1};" : "=l"(d) : "f"(x))
#define UNPACK2(lo, hi, v) asm("mov.b64 {%0, %1}, %2;" : "=f"(lo), "=f"(hi) : "l"(v))

// cp.async (LDGSTS) helpers: .cg = L2-only (required for cross-SM h coherence)
#define CP_ASYNC16(smem_u32, gptr) \
    asm volatile("cp.async.cg.shared.global [%0], [%1], 16;" :: "r"(smem_u32), "l"(gptr) : "memory")
#define CP_COMMIT() asm volatile("cp.async.commit_group;" ::: "memory")
#define CP_WAIT(n)  asm volatile("cp.async.wait_group %0;" :: "n"(n) : "memory")

__device__ __forceinline__ float tanh_fast(float x) {
    float y;
    asm("tanh.approx.f32 %0, %1;" : "=f"(y) : "f"(x));
    return y;
}
__device__ __forceinline__ float sig_fast(float x) {
    return fmaf(0.5f, tanh_fast(0.5f * x), 0.5f);
}

// ---------------- scratch (device globals; no allocation allowed) ----------
__device__ float g_x[2 * LL * BB * EE];          // embedded inputs  (33.5 MB)
__device__ float g_xg[(size_t)2 * LL * BB * NG]; // input-gate GEMM out (134 MB)
__device__ float g_o[2 * LL * BB * DD];          // o1, o2 outputs (L,B,D) (33.5 MB)
__device__ float g_h[2 * 4 * BB * HH];           // double-buffered h state (1 MB)
__device__ float g_mp1[BB * DD];
__device__ float g_attsm[BB * LL];
__device__ unsigned g_syncs[4 * 32];             // per-scan barrier counters (128B apart)
__device__ unsigned g_dones[4 * 32];             // per-scan reset counters

// ---------------- kernel 0: zero h state ----------------
__global__ void zero_h_kernel() {
    int i = blockIdx.x * blockDim.x + threadIdx.x;
    if (i < 2 * 4 * BB * HH) g_h[i] = 0.0f;
}

// ---------------- kernel 1: embedding gather ----------------
__global__ void gather_kernel(const int* __restrict__ t1, const int* __restrict__ t2,
                              const float* __restrict__ emb) {
    int row = blockIdx.x;            // 0..16383
    int s   = row >> 13;
    int r   = row & 8191;
    int tok = s ? t2[r] : t1[r];
    const float4* src = (const float4*)(emb + (size_t)tok * EE);
    float4* dst = (float4*)(g_x + (size_t)row * EE);
    int tid = threadIdx.x;           // 128 threads, 128 float4 per row
    dst[tid] = src[tid];
}

// ---------------- kernel 2: input projection GEMM ----------------
// (f32x2 packed, BK=16, register-staged double-buffered smem pipeline)
#define GTILE (16 * 132)

__global__ __launch_bounds__(256) void gemm_kernel(
    const float* __restrict__ Wf, const float* __restrict__ Wb,
    const float* __restrict__ bihf, const float* __restrict__ bhhf,
    const float* __restrict__ bihb, const float* __restrict__ bhhb) {
    extern __shared__ float gsm[];
    float* As0 = gsm;                  // [2][16][132]
    float* Bs0 = gsm + 2 * GTILE;      // [2][16][132]

    int bm = blockIdx.x;             // 0..127  (M tiles)
    int bn = blockIdx.y;             // 0..15   (N tiles of 128)
    int n0 = bn * 128;
    int dirb = (n0 >= 1024) ? 1 : 0;
    const float* W = dirb ? Wb : Wf;
    int nW0 = dirb ? (n0 - 1024) : n0;

    const float* A = g_x + (size_t)bm * 128 * EE;
    int tid = threadIdx.x;
    int tr = tid >> 4;               // 0..15 -> rows r0..r0+7 (4 packed pairs)
    int tc = tid & 15;               // 0..15 -> cols c0..c0+7
    int r0 = tr * 8, c0 = tc * 8;

    const int ar0 = tid >> 2,         ak0 = tid & 3;
    const int ar1 = (tid + 256) >> 2, ak1 = tid & 3;

    ull acc2[4][8];
#pragma unroll
    for (int p = 0; p < 4; p++)
#pragma unroll
        for (int c = 0; c < 8; c++) acc2[p][c] = 0ULL;

    float4 aR[2], bR[2];
    aR[0] = *(const float4*)(A + (size_t)ar0 * EE + ak0 * 4);
    aR[1] = *(const float4*)(A + (size_t)ar1 * EE + ak1 * 4);
    bR[0] = *(const float4*)(W + (size_t)(nW0 + ar0) * EE + ak0 * 4);
    bR[1] = *(const float4*)(W + (size_t)(nW0 + ar1) * EE + ak1 * 4);
    {
        float* Ad = As0;  float* Bd = Bs0;
        Ad[(ak0 * 4 + 0) * 132 + ar0] = aR[0].x; Ad[(ak0 * 4 + 1) * 132 + ar0] = aR[0].y;
        Ad[(ak0 * 4 + 2) * 132 + ar0] = aR[0].z; Ad[(ak0 * 4 + 3) * 132 + ar0] = aR[0].w;
        Ad[(ak1 * 4 + 0) * 132 + ar1] = aR[1].x; Ad[(ak1 * 4 + 1) * 132 + ar1] = aR[1].y;
        Ad[(ak1 * 4 + 2) * 132 + ar1] = aR[1].z; Ad[(ak1 * 4 + 3) * 132 + ar1] = aR[1].w;
        Bd[(ak0 * 4 + 0) * 132 + ar0] = bR[0].x; Bd[(ak0 * 4 + 1) * 132 + ar0] = bR[0].y;
        Bd[(ak0 * 4 + 2) * 132 + ar0] = bR[0].z; Bd[(ak0 * 4 + 3) * 132 + ar0] = bR[0].w;
        Bd[(ak1 * 4 + 0) * 132 + ar1] = bR[1].x; Bd[(ak1 * 4 + 1) * 132 + ar1] = bR[1].y;
        Bd[(ak1 * 4 + 2) * 132 + ar1] = bR[1].z; Bd[(ak1 * 4 + 3) * 132 + ar1] = bR[1].w;
    }

    for (int it = 0; it < 32; ++it) {
        __syncthreads();
        if (it < 31) {
            int kn = (it + 1) * 16;
            aR[0] = *(const float4*)(A + (size_t)ar0 * EE + kn + ak0 * 4);
            aR[1] = *(const float4*)(A + (size_t)ar1 * EE + kn + ak1 * 4);
            bR[0] = *(const float4*)(W + (size_t)(nW0 + ar0) * EE + kn + ak0 * 4);
            bR[1] = *(const float4*)(W + (size_t)(nW0 + ar1) * EE + kn + ak1 * 4);
        }

        const float* Asc = As0 + (it & 1) * GTILE;
        const float* Bsc = Bs0 + (it & 1) * GTILE;
#pragma unroll
        for (int kk = 0; kk < 16; kk++) {
            ull apair[4];
            {
                ulonglong2 a0 = *(const ulonglong2*)&Asc[kk * 132 + r0];
                ulonglong2 a1 = *(const ulonglong2*)&Asc[kk * 132 + r0 + 4];
                apair[0] = a0.x; apair[1] = a0.y; apair[2] = a1.x; apair[3] = a1.y;
            }
            float4 bv0 = *(const float4*)&Bsc[kk * 132 + c0];
            float4 bv1 = *(const float4*)&Bsc[kk * 132 + c0 + 4];
            ull bd[8];
            DUP2(bd[0], bv0.x); DUP2(bd[1], bv0.y); DUP2(bd[2], bv0.z); DUP2(bd[3], bv0.w);
            DUP2(bd[4], bv1.x); DUP2(bd[5], bv1.y); DUP2(bd[6], bv1.z); DUP2(bd[7], bv1.w);
#pragma unroll
            for (int p = 0; p < 4; p++)
#pragma unroll
                for (int c = 0; c < 8; c++)
                    FMA2(acc2[p][c], apair[p], bd[c]);
        }

        if (it < 31) {
            float* Ad = As0 + ((it + 1) & 1) * GTILE;
            float* Bd = Bs0 + ((it + 1) & 1) * GTILE;
            Ad[(ak0 * 4 + 0) * 132 + ar0] = aR[0].x; Ad[(ak0 * 4 + 1) * 132 + ar0] = aR[0].y;
            Ad[(ak0 * 4 + 2) * 132 + ar0] = aR[0].z; Ad[(ak0 * 4 + 3) * 132 + ar0] = aR[0].w;
            Ad[(ak1 * 4 + 0) * 132 + ar1] = aR[1].x; Ad[(ak1 * 4 + 1) * 132 + ar1] = aR[1].y;
            Ad[(ak1 * 4 + 2) * 132 + ar1] = aR[1].z; Ad[(ak1 * 4 + 3) * 132 + ar1] = aR[1].w;
            Bd[(ak0 * 4 + 0) * 132 + ar0] = bR[0].x; Bd[(ak0 * 4 + 1) * 132 + ar0] = bR[0].y;
            Bd[(ak0 * 4 + 2) * 132 + ar0] = bR[0].z; Bd[(ak0 * 4 + 3) * 132 + ar0] = bR[0].w;
            Bd[(ak1 * 4 + 0) * 132 + ar1] = bR[1].x; Bd[(ak1 * 4 + 1) * 132 + ar1] = bR[1].y;
            Bd[(ak1 * 4 + 2) * 132 + ar1] = bR[1].z; Bd[(ak1 * 4 + 3) * 132 + ar1] = bR[1].w;
        }
    }

    float bs[8];
#pragma unroll
    for (int c = 0; c < 8; c++) {
        int n = n0 + c0 + c;
        bs[c] = dirb ? (bihb[n - 1024] + bhhb[n - 1024]) : (bihf[n] + bhhf[n]);
    }
#pragma unroll
    for (int p = 0; p < 4; p++) {
        float lo[8], hi[8];
#pragma unroll
        for (int c = 0; c < 8; c++) {
            UNPACK2(lo[c], hi[c], acc2[p][c]);
            lo[c] += bs[c]; hi[c] += bs[c];
        }
        size_t row_lo = (size_t)(bm * 128 + r0 + 2 * p) * NG + n0 + c0;
        size_t row_hi = row_lo + NG;
        *(float4*)(g_xg + row_lo)     = make_float4(lo[0], lo[1], lo[2], lo[3]);
        *(float4*)(g_xg + row_lo + 4) = make_float4(lo[4], lo[5], lo[6], lo[7]);
        *(float4*)(g_xg + row_hi)     = make_float4(hi[0], hi[1], hi[2], hi[3]);
        *(float4*)(g_xg + row_hi + 4) = make_float4(hi[4], hi[5], hi[6], hi[7]);
    }
}

// ---------------- kernel 3: persistent LSTM recurrence ----------------
// K-PACKED f32x2 accumulators: acc2[bi][g] holds (even-k, odd-k) partial sums,
// folded lo+hi at the end. Zero DUP/PACK in inner loop: both operands come
// packed straight out of LDS.128 (h is k-contiguous; Whh re-laid [unit][g][k]).
// 128 blocks = 4 scans x 32 slices; 256 threads (2 warps/SMSP).
// Thread (ct = tid&7 unit, bt = tid>>3 0..31): 4 batches (bt + 32*bi), 4 gates.
// Per-scan barrier: each scan's 32 blocks sync among themselves.
#define WST 1028                     // sh_w unit stride: 4112B % 128B = 16 -> conflict-free
#define HST 260                      // sh_h batch stride: 1040B % 128B = 16 -> conflict-free

__global__ __launch_bounds__(256, 1) void lstm_kernel(const float* __restrict__ Whh_f,
                                                      const float* __restrict__ Whh_b) {
    extern __shared__ float sm[];
    float* sh_w = sm;                     // [8 units][1028] : g*256 + k (k contiguous)
    float* sh_h = sm + 8 * WST;           // [128 batches][260] : k contiguous

    const int tid = threadIdx.x;
    const int rec = blockIdx.x >> 5;      // (s1,f)(s1,b)(s2,f)(s2,b)
    const int slice = blockIdx.x & 31;
    const int s = rec >> 1;
    const int dir = rec & 1;
    const int ct = tid & 7;               // unit within slice
    const int bt = tid >> 3;              // 0..31
    const int j = slice * 8 + ct;         // hidden unit 0..255
    const float* Whh = dir ? Whh_b : Whh_f;
    const unsigned shh_u32 = (unsigned)__cvta_generic_to_shared(sh_h);
    unsigned* syncp = &g_syncs[rec * 32];
    unsigned* donep = &g_dones[rec * 32];

    // Build weights: sh_w[jj*WST + g*256 + k] = Whh[g*256 + slice*8 + jj][k]
    for (int idx = tid; idx < 8 * 4 * 64; idx += 256) {
        int jj = idx >> 8;                // 0..7
        int g  = (idx >> 6) & 3;
        int k4 = idx & 63;
        float4 v = *(const float4*)(Whh + (size_t)(g * 256 + slice * 8 + jj) * HH + k4 * 4);
        *(float4*)(sh_w + jj * WST + g * 256 + k4 * 4) = v;
    }

    const float* wbase = sh_w + ct * WST;
    float c_st[4] = {0.f, 0.f, 0.f, 0.f};

    for (int t = 0; t < 64; ++t) {
        const int l = dir ? (63 - t) : t;

        // stage h_prev via cp.async.cg in two chunks (k 0..127 / 128..255)
        const float* hsrc = g_h + (size_t)((t & 1) * 4 + rec) * BB * HH;
#pragma unroll 4
        for (int it = 0; it < 16; it++) {           // chunk0: k4 0..31
            int idx = tid + 256 * it;               // 4096 float4
            int b = idx >> 5, k4 = idx & 31;
            CP_ASYNC16(shh_u32 + (unsigned)(b * HST + k4 * 4) * 4u,
                       hsrc + (size_t)b * HH + k4 * 4);
        }
        CP_COMMIT();
#pragma unroll 4
        for (int it = 0; it < 16; it++) {           // chunk1: k4 32..63
            int idx = tid + 256 * it;
            int b = idx >> 5, k4 = 32 + (idx & 31);
            CP_ASYNC16(shh_u32 + (unsigned)(b * HST + k4 * 4) * 4u,
                       hsrc + (size_t)b * HH + k4 * 4);
        }
        CP_COMMIT();

        // xg prefetch (independent LDGs, overlap with cp.async)
        const float* xgp = g_xg + ((size_t)(s * 8192 + l * 128)) * NG + dir * 1024 + j;
        float xv0[4], xv1[4], xv2[4], xv3[4];
#pragma unroll
        for (int g = 0; g < 4; g++) {
            xv0[g] = __ldcg(xgp + (size_t)bt * NG + g * 256);
            xv1[g] = __ldcg(xgp + (size_t)(bt + 32) * NG + g * 256);
            xv2[g] = __ldcg(xgp + (size_t)(bt + 64) * NG + g * 256);
            xv3[g] = __ldcg(xgp + (size_t)(bt + 96) * NG + g * 256);
        }

        // k-packed accumulators: acc2[bi][g] = (sum over even k, sum over odd k)
        ull acc2[4][4];
#pragma unroll
        for (int bi = 0; bi < 4; bi++)
#pragma unroll
            for (int g = 0; g < 4; g++) acc2[bi][g] = 0ULL;

        CP_WAIT(1);          // chunk0 landed
        __syncthreads();

        // first half (k4 0..31) while chunk1 streams
#pragma unroll 4
        for (int k4 = 0; k4 < 32; ++k4) {
            ulonglong2 hp[4], wp[4];
#pragma unroll
            for (int bi = 0; bi < 4; bi++)
                hp[bi] = *(const ulonglong2*)(sh_h + (bt + 32 * bi) * HST + k4 * 4);
#pragma unroll
            for (int g = 0; g < 4; g++)
                wp[g] = *(const ulonglong2*)(wbase + g * 256 + k4 * 4);
#pragma unroll
            for (int bi = 0; bi < 4; bi++)
#pragma unroll
                for (int g = 0; g < 4; g++) {
                    FMA2(acc2[bi][g], hp[bi].x, wp[g].x);
                    FMA2(acc2[bi][g], hp[bi].y, wp[g].y);
                }
        }

        CP_WAIT(0);          // chunk1 landed
        __syncthreads();

        // second half (k4 32..63)
#pragma unroll 4
        for (int k4 = 32; k4 < 64; ++k4) {
            ulonglong2 hp[4], wp[4];
#pragma unroll
            for (int bi = 0; bi < 4; bi++)
                hp[bi] = *(const ulonglong2*)(sh_h + (bt + 32 * bi) * HST + k4 * 4);
#pragma unroll
            for (int g = 0; g < 4; g++)
                wp[g] = *(const ulonglong2*)(wbase + g * 256 + k4 * 4);
#pragma unroll
            for (int bi = 0; bi < 4; bi++)
#pragma unroll
                for (int g = 0; g < 4; g++) {
                    FMA2(acc2[bi][g], hp[bi].x, wp[g].x);
                    FMA2(acc2[bi][g], hp[bi].y, wp[g].y);
                }
        }

        // fold even/odd sums + xg, nonlinearity, state update, writes
        float* hdst = g_h + (size_t)(((t + 1) & 1) * 4 + rec) * BB * HH;
        float* odst = g_o + (size_t)s * LL * BB * DD + (size_t)l * BB * DD + dir * HH + j;
#pragma unroll
        for (int bi = 0; bi < 4; bi++) {
            int b = bt + 32 * bi;
            const float* xv = (bi == 0) ? xv0 : (bi == 1) ? xv1 : (bi == 2) ? xv2 : xv3;
            float gate[4];
#pragma unroll
            for (int g = 0; g < 4; g++) {
                float lo, hi;
                UNPACK2(lo, hi, acc2[bi][g]);
                gate[g] = xv[g] + lo + hi;
            }
            float ig = sig_fast(gate[0]);
            float fg = sig_fast(gate[1]);
            float gg = tanh_fast(gate[2]);
            float og = sig_fast(gate[3]);
            float c = fmaf(fg, c_st[bi], ig * gg);
            c_st[bi] = c;
            float h = og * tanh_fast(c);
            hdst[(size_t)b * HH + j] = h;
            odst[(size_t)b * DD] = h;
        }

        // per-scan barrier (32 blocks of this scan, all co-resident)
        __syncthreads();   // all threads' stores issued before arrival
        if (tid == 0) {
            __threadfence();
            atomicAdd(syncp, 1u);
            unsigned target = 32u * (unsigned)(t + 1);
            while (*((volatile unsigned*)syncp) < target) { }
            __threadfence();
        }
        __syncthreads();
    }

    // self-reset for graph replays (per scan)
    if (tid == 0) {
        unsigned old = atomicAdd(donep, 1u);
        if (old == 31u) {
            *donep = 0u;
            *syncp = 0u;
            __threadfence();
        }
    }
}

// ---------------- kernel 4: mp1 = max over time of o1 ----------------
__global__ void mp1_kernel() {
    int b = blockIdx.x;
    for (int d = threadIdx.x; d < DD; d += blockDim.x) {
        float m = -FLT_MAX;
#pragma unroll 8
        for (int l = 0; l < LL; l++)
            m = fmaxf(m, g_o[(size_t)l * BB * DD + b * DD + d]);
        g_mp1[b * DD + d] = m;
    }
}

// ---------------- kernel 5: attention + softmax (raw-reshape semantics) ----
// 256 threads: l = tid&63, d-part = tid>>6 (4 partials of 128 d each)
__global__ void att_kernel() {
    __shared__ float smp[DD];
    __shared__ float spart[4][LL];
    __shared__ float sat[LL];
    int b = blockIdx.x, tid = threadIdx.x;
    int l = tid & 63, part = tid >> 6;
    const float* o2 = g_o + (size_t)LL * BB * DD;
    for (int d = tid; d < DD; d += 256) smp[d] = g_mp1[b * DD + d];
    __syncthreads();
    float a = 0.0f;
    const float* o2b = o2 + (size_t)b * DD * LL + l;
    for (int d = part * 128; d < part * 128 + 128; d++)
        a = fmaf(smp[d], o2b[(size_t)d * LL], a);
    spart[part][l] = a;
    __syncthreads();
    if (tid < LL) {
        float at = spart[0][tid] + spart[1][tid] + spart[2][tid] + spart[3][tid];
        sat[tid] = at;
    }
    __syncthreads();
    if (tid < LL) {
        float mx = -FLT_MAX;
        for (int i = 0; i < LL; i++) mx = fmaxf(mx, sat[i]);
        float ssum = 0.0f;
        for (int i = 0; i < LL; i++) ssum += expf(sat[i] - mx);
        g_attsm[b * LL + tid] = expf(sat[tid] - mx) / ssum;
    }
}

// ---------------- kernel 6: new_pool + sim (fused) ----------------
__global__ void sim_kernel(float* __restrict__ out) {
    __shared__ float sal[LL];
    __shared__ float red[256];
    int b = blockIdx.x, tid = threadIdx.x;
    if (tid < LL) sal[tid] = g_attsm[b * LL + tid];
    __syncthreads();
    const float* o2 = g_o + (size_t)LL * BB * DD;
    float local = 0.0f;
    for (int d = tid; d < DD; d += 256) {
        float np = 0.0f;
#pragma unroll 8
        for (int l = 0; l < LL; l++)
            np = fmaf(sal[l], o2[(size_t)b * LL * DD + l * DD + d], np);
        local += fabsf(g_mp1[b * DD + d] - np);
    }
    red[tid] = local;
    __syncthreads();
    for (int s2 = 128; s2 > 0; s2 >>= 1) {
        if (tid < s2) red[tid] += red[tid + s2];
        __syncthreads();
    }
    if (tid == 0) out[b] = expf(-red[0]);
}

// ---------------- kernel 7: commonWords + e1h/e2h ----------------
__global__ void e_kernel(const int* __restrict__ t1, const int* __restrict__ t2,
                         float* __restrict__ out) {
    __shared__ int s1[LL];
    __shared__ int spos[LL];
    __shared__ int smask[LL];
    __shared__ int shas;
    int b = blockIdx.x, tid = threadIdx.x;
    if (tid == 0) shas = 0;
    if (tid < LL) s1[tid] = t1[tid * BB + b];
    __syncthreads();
    if (tid < LL) {
        int tok2 = t2[tid * BB + b];
        int d = -1;
        for (int jj = 0; jj < LL; jj++)
            if (s1[jj] == tok2) d = jj;
        int m = (d > 1) && (tok2 > 0);
        smask[tid] = m;
        spos[tid] = min(max(d, 0), LL - 1);
        if (m) atomicOr(&shas, 1);
    }
    __syncthreads();
    int has = shas;
    const float* o1 = g_o;
    const float* o2 = g_o + (size_t)LL * BB * DD;
    for (int d = tid; d < DD; d += 256) {
        float m1 = -FLT_MAX, m2 = -FLT_MAX;
        for (int i = 0; i < LL; i++) {
            if (smask[i]) {
                m1 = fmaxf(m1, o1[(size_t)spos[i] * BB * DD + b * DD + d]);
                m2 = fmaxf(m2, o2[(size_t)i * BB * DD + b * DD + d]);
            }
        }
        out[128 + b * DD + d] = has ? m1 : 0.0f;
        out[128 + BB * DD + b * DD + d] = has ? m2 : 0.0f;
    }
}

// ---------------- launch ----------------
extern "C" void kernel_launch(void* const* d_in, const int* in_sizes, int n_in,
                              void* d_out, int out_size) {
    const int* t1 = (const int*)d_in[0];
    const int* t2 = (const int*)d_in[1];
    const float* emb = (const float*)d_in[2];
    const float* Wihf = (const float*)d_in[3];
    const float* Whhf = (const float*)d_in[4];
    const float* bihf = (const float*)d_in[5];
    const float* bhhf = (const float*)d_in[6];
    const float* Wihb = (const float*)d_in[7];
    const float* Whhb = (const float*)d_in[8];
    const float* bihb = (const float*)d_in[9];
    const float* bhhb = (const float*)d_in[10];
    float* out = (float*)d_out;

    zero_h_kernel<<<(2 * 4 * BB * HH + 255) / 256, 256>>>();
    gather_kernel<<<NROWS, 128>>>(t1, t2, emb);

    const int gemm_smem = 4 * GTILE * 4;   // 67,584 B
    cudaFuncSetAttribute(gemm_kernel, cudaFuncAttributeMaxDynamicSharedMemorySize, gemm_smem);
    dim3 ggrid(128, 16);
    gemm_kernel<<<ggrid, 256, gemm_smem>>>(Wihf, Wihb, bihf, bhhf, bihb, bhhb);

    const int lstm_smem = (8 * WST + 128 * HST) * 4;  // 166,016 B
    cudaFuncSetAttribute(lstm_kernel, cudaFuncAttributeMaxDynamicSharedMemorySize, lstm_smem);
    lstm_kernel<<<128, 256, lstm_smem>>>(Whhf, Whhb);

    mp1_kernel<<<BB, 128>>>();
    att_kernel<<<BB, 256>>>();
    sim_kernel<<<BB, 256>>>(out);
    e_kernel<<<BB, 256>>>(t1, t2, out);
}